// round 2
// baseline (speedup 1.0000x reference)
#include <cuda_runtime.h>
#include <math.h>

// ---------------- problem constants ----------------
#define B_  2
#define H_  64
#define W_  64
#define C_  96
#define DIN 192
#define NST 16
#define RNK 6
#define K_  4
#define L_  4096          // H_*W_
#define NC  32            // scan chunks
#define LC  128           // L_/NC
#define NR  38            // RNK + 2*NST

// ---------------- scratch (device globals; no runtime alloc) ----------------
static __device__ float g_xcpre[B_*L_*DIN];          // in-proj x half, (b,l,d)
static __device__ float g_xconv[B_*L_*DIN];          // conv+SiLU out,  (b,l,d)
static __device__ float g_z    [B_*L_*DIN];          // gate z,         (b,l,d)
static __device__ float g_xdbl [B_*K_*NR*L_];        // x_proj out, ((b*K+k)*38+r)*L + l
static __device__ float g_chP  [B_*K_*NC*DIN*NST];   // per-chunk prod(dA)
static __device__ float g_chQ  [B_*K_*NC*DIN*NST];   // per-chunk affine offset
static __device__ float g_h0   [B_*K_*NC*DIN*NST];   // chunk initial states
static __device__ float g_y    [B_*K_*L_*DIN];       // scattered ys, ((b*K+k)*L + pos)*DIN + d
static __device__ float g_psum [B_*K_*NC*DIN];       // per-chunk pooled partial sums
static __device__ float g_gate [B_*DIN*K_];          // sigmoid gates

// ---------------- kernel 1: in_proj GEMM  (8192x384x96) ----------------
// C[m,n] = sum_k x[m,k] * W_in[n,k];  n<192 -> g_xcpre, else -> g_z
__global__ __launch_bounds__(256) void k_inproj(const float* __restrict__ x,
                                                const float* __restrict__ Win) {
    __shared__ float As[32][68];
    __shared__ float Bs[32][68];
    int tid = threadIdx.x;
    int m0 = blockIdx.y * 64;
    int n0 = blockIdx.x * 64;
    int tm = tid & 15, tn = tid >> 4;
    float acc[4][4] = {};
    for (int k0 = 0; k0 < 96; k0 += 32) {
        #pragma unroll
        for (int q = 0; q < 2; q++) {
            int f = tid * 2 + q;               // 0..511 float4s
            int m = f >> 3, kq = f & 7;
            float4 v = *(const float4*)&x[(size_t)(m0 + m) * 96 + k0 + kq * 4];
            As[kq*4+0][m] = v.x; As[kq*4+1][m] = v.y;
            As[kq*4+2][m] = v.z; As[kq*4+3][m] = v.w;
        }
        #pragma unroll
        for (int q = 0; q < 2; q++) {
            int f = tid * 2 + q;
            int n = f >> 3, kq = f & 7;
            float4 v = *(const float4*)&Win[(size_t)(n0 + n) * 96 + k0 + kq * 4];
            Bs[kq*4+0][n] = v.x; Bs[kq*4+1][n] = v.y;
            Bs[kq*4+2][n] = v.z; Bs[kq*4+3][n] = v.w;
        }
        __syncthreads();
        #pragma unroll
        for (int kk = 0; kk < 32; kk++) {
            float4 a4 = *(const float4*)&As[kk][tm*4];
            float4 b4 = *(const float4*)&Bs[kk][tn*4];
            float av[4] = {a4.x, a4.y, a4.z, a4.w};
            float bv[4] = {b4.x, b4.y, b4.z, b4.w};
            #pragma unroll
            for (int i = 0; i < 4; i++)
                #pragma unroll
                for (int j = 0; j < 4; j++)
                    acc[i][j] = fmaf(av[i], bv[j], acc[i][j]);
        }
        __syncthreads();
    }
    #pragma unroll
    for (int i = 0; i < 4; i++) {
        int m = m0 + tm * 4 + i;
        #pragma unroll
        for (int j = 0; j < 4; j++) {
            int n = n0 + tn * 4 + j;
            if (n < DIN) g_xcpre[(size_t)m * DIN + n]        = acc[i][j];
            else         g_z    [(size_t)m * DIN + (n - DIN)] = acc[i][j];
        }
    }
}

// ---------------- kernel 2: depthwise 3x3 conv + bias + SiLU ----------------
__global__ __launch_bounds__(192) void k_conv(const float* __restrict__ cw,
                                              const float* __restrict__ cb) {
    int d = threadIdx.x;
    int b = blockIdx.z, y = blockIdx.y, xt = blockIdx.x;   // xt: 0..3 (16 cols each)
    float w9[9];
    #pragma unroll
    for (int i = 0; i < 9; i++) w9[i] = cw[d * 9 + i];
    float bias = cb[d];
    const float* src = g_xcpre + (size_t)b * L_ * DIN;
    float*       dst = g_xconv + (size_t)b * L_ * DIN;
    for (int xi = 0; xi < 16; xi++) {
        int xx0 = xt * 16 + xi;
        float acc = bias;
        #pragma unroll
        for (int dy = -1; dy <= 1; dy++) {
            int yy = y + dy;
            if ((unsigned)yy >= 64u) continue;
            #pragma unroll
            for (int dx = -1; dx <= 1; dx++) {
                int xx = xx0 + dx;
                if ((unsigned)xx >= 64u) continue;
                acc = fmaf(src[(size_t)(yy * 64 + xx) * DIN + d], w9[(dy+1)*3 + dx+1], acc);
            }
        }
        float s = 1.f / (1.f + __expf(-acc));
        dst[(size_t)(y * 64 + xx0) * DIN + d] = acc * s;
    }
}

// ---------------- kernel 3: x_proj GEMM with gather (per (b,k): 38 x 4096 x 192) ---
__global__ __launch_bounds__(128) void k_xproj(const float* __restrict__ xpw,
                                               const int*   __restrict__ scan) {
    __shared__ float xs_s[32][68];   // [kk][l]
    __shared__ float ws  [40][33];   // [r][kk], rows 38/39 zeroed
    __shared__ int   sid [64];
    int tid = threadIdx.x;
    int l0  = blockIdx.x * 64;
    int bk  = blockIdx.y;
    int b = bk >> 2, k = bk & 3;
    if (tid < 64) sid[tid] = scan[(size_t)k * L_ + l0 + tid];
    int lg = tid >> 3, rg = tid & 7;        // 16 l-groups x 8 r-groups
    float acc[5][4] = {};
    const float* xc = g_xconv + (size_t)b * L_ * DIN;
    for (int k0 = 0; k0 < DIN; k0 += 32) {
        __syncthreads();
        for (int i = tid; i < NR * 32; i += 128) {
            int r = i >> 5, c = i & 31;
            ws[r][c] = xpw[(size_t)(k * NR + r) * DIN + k0 + c];
        }
        if (tid < 64) ws[38 + (tid >> 5)][tid & 31] = 0.f;
        {
            int l = tid >> 1, half = (tid & 1) * 16;
            const float* p = &xc[(size_t)sid[l] * DIN + k0 + half];
            #pragma unroll
            for (int q = 0; q < 16; q += 4) {
                float4 v = *(const float4*)(p + q);
                xs_s[half+q+0][l] = v.x; xs_s[half+q+1][l] = v.y;
                xs_s[half+q+2][l] = v.z; xs_s[half+q+3][l] = v.w;
            }
        }
        __syncthreads();
        #pragma unroll
        for (int kk = 0; kk < 32; kk++) {
            float4 a4 = *(const float4*)&xs_s[kk][lg * 4];
            float av[4] = {a4.x, a4.y, a4.z, a4.w};
            #pragma unroll
            for (int j = 0; j < 5; j++) {
                float wv = ws[rg + 8 * j][kk];
                #pragma unroll
                for (int i = 0; i < 4; i++) acc[j][i] = fmaf(wv, av[i], acc[j][i]);
            }
        }
    }
    float* outp = g_xdbl + (size_t)bk * NR * L_;
    #pragma unroll
    for (int j = 0; j < 5; j++) {
        int r = rg + 8 * j;
        if (r < NR) {
            #pragma unroll
            for (int i = 0; i < 4; i++)
                outp[(size_t)r * L_ + l0 + lg * 4 + i] = acc[j][i];
        }
    }
}

// ---------------- softplus helper ----------------
__device__ __forceinline__ float softplusf(float t) {
    return (t > 15.f) ? t : log1pf(expf(t));
}

// ---------------- kernel 4: scan phase A (per-chunk transitions) -------------
__global__ __launch_bounds__(192) void k_scanA(const float* __restrict__ dtw,
                                               const float* __restrict__ dtb,
                                               const float* __restrict__ Alogs,
                                               const int*   __restrict__ scan) {
    __shared__ float sx[NR][LC];
    __shared__ int   ssid[LC];
    int d  = threadIdx.x;
    int c  = blockIdx.x;
    int bk = blockIdx.y;
    int b = bk >> 2, k = bk & 3;
    int l0 = c * LC;
    const float* xd = g_xdbl + (size_t)bk * NR * L_;
    for (int i = d; i < NR * LC; i += 192) {
        int r = i >> 7, q = i & 127;
        sx[r][q] = xd[(size_t)r * L_ + l0 + q];
    }
    for (int i = d; i < LC; i += 192) ssid[i] = scan[(size_t)k * L_ + l0 + i];
    int kd = k * DIN + d;
    float wr[RNK];
    #pragma unroll
    for (int r = 0; r < RNK; r++) wr[r] = dtw[(size_t)kd * RNK + r];
    float tb = dtb[kd];
    float a[NST]; bool fast = true;
    #pragma unroll
    for (int n = 0; n < NST; n++) {
        a[n] = -expf(Alogs[(size_t)kd * NST + n]);
        fast = fast && (fabsf(a[n] + (float)(n + 1)) <= 1e-3f * (float)(n + 1));
    }
    __syncthreads();
    const float* xc = g_xconv + (size_t)b * L_ * DIN;
    float h[NST], P[NST];
    #pragma unroll
    for (int n = 0; n < NST; n++) { h[n] = 0.f; P[n] = 1.f; }
    if (fast) {
        #pragma unroll 1
        for (int i = 0; i < LC; i++) {
            float xv = xc[(size_t)ssid[i] * DIN + d];
            float t = tb;
            #pragma unroll
            for (int r = 0; r < RNK; r++) t = fmaf(wr[r], sx[r][i], t);
            float delta = softplusf(t);
            float du = delta * xv;
            float w = expf(-delta);
            float pw = 1.f;
            #pragma unroll
            for (int n = 0; n < NST; n++) {
                pw *= w;
                h[n] = fmaf(pw, h[n], du * sx[RNK + n][i]);
                P[n] *= pw;
            }
        }
    } else {
        #pragma unroll 1
        for (int i = 0; i < LC; i++) {
            float xv = xc[(size_t)ssid[i] * DIN + d];
            float t = tb;
            #pragma unroll
            for (int r = 0; r < RNK; r++) t = fmaf(wr[r], sx[r][i], t);
            float delta = softplusf(t);
            float du = delta * xv;
            #pragma unroll
            for (int n = 0; n < NST; n++) {
                float dA = __expf(delta * a[n]);
                h[n] = fmaf(dA, h[n], du * sx[RNK + n][i]);
                P[n] *= dA;
            }
        }
    }
    size_t base = ((size_t)(bk * NC + c) * DIN + d) * NST;
    #pragma unroll
    for (int n = 0; n < NST; n++) { g_chP[base + n] = P[n]; g_chQ[base + n] = h[n]; }
}

// ---------------- kernel 5: scan phase B (serial chunk chain, 1536 lanes) ----
__global__ __launch_bounds__(192) void k_scanB() {
    int bk = blockIdx.x;         // 0..7 = (b,k)
    int d  = threadIdx.x;
    float h[NST];
    #pragma unroll
    for (int n = 0; n < NST; n++) h[n] = 0.f;
    for (int c = 0; c < NC; c++) {
        size_t base = ((size_t)(bk * NC + c) * DIN + d) * NST;
        #pragma unroll
        for (int n = 0; n < NST; n++) g_h0[base + n] = h[n];
        #pragma unroll
        for (int n = 0; n < NST; n++) h[n] = fmaf(g_chP[base + n], h[n], g_chQ[base + n]);
    }
}

// ---------------- kernel 6: scan phase C (replay + ys + scatter + pool) ------
__global__ __launch_bounds__(192) void k_scanC(const float* __restrict__ dtw,
                                               const float* __restrict__ dtb,
                                               const float* __restrict__ Alogs,
                                               const float* __restrict__ Dsv,
                                               const int*   __restrict__ scan) {
    __shared__ float sx[NR][LC];
    __shared__ int   ssid[LC];
    int d  = threadIdx.x;
    int c  = blockIdx.x;
    int bk = blockIdx.y;
    int b = bk >> 2, k = bk & 3;
    int l0 = c * LC;
    const float* xd = g_xdbl + (size_t)bk * NR * L_;
    for (int i = d; i < NR * LC; i += 192) {
        int r = i >> 7, q = i & 127;
        sx[r][q] = xd[(size_t)r * L_ + l0 + q];
    }
    for (int i = d; i < LC; i += 192) ssid[i] = scan[(size_t)k * L_ + l0 + i];
    int kd = k * DIN + d;
    float wr[RNK];
    #pragma unroll
    for (int r = 0; r < RNK; r++) wr[r] = dtw[(size_t)kd * RNK + r];
    float tb = dtb[kd];
    float Dv = Dsv[kd];
    float a[NST]; bool fast = true;
    #pragma unroll
    for (int n = 0; n < NST; n++) {
        a[n] = -expf(Alogs[(size_t)kd * NST + n]);
        fast = fast && (fabsf(a[n] + (float)(n + 1)) <= 1e-3f * (float)(n + 1));
    }
    float h[NST];
    {
        size_t base = ((size_t)(bk * NC + c) * DIN + d) * NST;
        #pragma unroll
        for (int n = 0; n < NST; n++) h[n] = g_h0[base + n];
    }
    __syncthreads();
    const float* xc = g_xconv + (size_t)b * L_ * DIN;
    float* yp = g_y + (size_t)bk * L_ * DIN;
    float sacc = 0.f;
    if (fast) {
        #pragma unroll 1
        for (int i = 0; i < LC; i++) {
            float xv = xc[(size_t)ssid[i] * DIN + d];
            float t = tb;
            #pragma unroll
            for (int r = 0; r < RNK; r++) t = fmaf(wr[r], sx[r][i], t);
            float delta = softplusf(t);
            float du = delta * xv;
            float w = expf(-delta);
            float pw = 1.f;
            float ys = 0.f;
            #pragma unroll
            for (int n = 0; n < NST; n++) {
                pw *= w;
                h[n] = fmaf(pw, h[n], du * sx[RNK + n][i]);
                ys = fmaf(h[n], sx[RNK + NST + n][i], ys);
            }
            ys = fmaf(Dv, xv, ys);
            yp[(size_t)ssid[i] * DIN + d] = ys;
            sacc += ys;
        }
    } else {
        #pragma unroll 1
        for (int i = 0; i < LC; i++) {
            float xv = xc[(size_t)ssid[i] * DIN + d];
            float t = tb;
            #pragma unroll
            for (int r = 0; r < RNK; r++) t = fmaf(wr[r], sx[r][i], t);
            float delta = softplusf(t);
            float du = delta * xv;
            float ys = 0.f;
            #pragma unroll
            for (int n = 0; n < NST; n++) {
                float dA = __expf(delta * a[n]);
                h[n] = fmaf(dA, h[n], du * sx[RNK + n][i]);
                ys = fmaf(h[n], sx[RNK + NST + n][i], ys);
            }
            ys = fmaf(Dv, xv, ys);
            yp[(size_t)ssid[i] * DIN + d] = ys;
            sacc += ys;
        }
    }
    g_psum[(size_t)(bk * NC + c) * DIN + d] = sacc;
}

// ---------------- kernel 7: gates (deterministic pooled reduce) --------------
__global__ __launch_bounds__(192) void k_gate(const float* __restrict__ gw,
                                              const float* __restrict__ gb) {
    int b = blockIdx.x, d = threadIdx.x;
    float pooled[K_];
    #pragma unroll
    for (int k = 0; k < K_; k++) {
        float s = 0.f;
        for (int c = 0; c < NC; c++)
            s += g_psum[(size_t)((b * K_ + k) * NC + c) * DIN + d];
        pooled[k] = s * (1.f / (float)L_);
    }
    #pragma unroll
    for (int o = 0; o < K_; o++) {
        float acc = gb[d * K_ + o];
        #pragma unroll
        for (int i = 0; i < K_; i++)
            acc = fmaf(pooled[i], gw[(size_t)(d * K_ + o) * K_ + i], acc);
        g_gate[(size_t)(b * DIN + d) * K_ + o] = 1.f / (1.f + __expf(-acc));
    }
}

// ---------------- kernel 8: gate-combine + LayerNorm + SiLU(z) + out GEMM ----
__global__ __launch_bounds__(256) void k_final(const float* __restrict__ lng,
                                               const float* __restrict__ lnb,
                                               const float* __restrict__ Wout,
                                               float* __restrict__ out) {
    __shared__ float a_s[32][193];
    __shared__ float w_s[96][33];
    int tid = threadIdx.x;
    int b  = blockIdx.y;
    int l0 = blockIdx.x * 32;
    int lt = tid >> 3, st = tid & 7;
    int l = l0 + lt;
    float s1 = 0.f, s2 = 0.f;
    #pragma unroll
    for (int q = 0; q < 24; q++) {
        int d = st + 8 * q;
        float4 gt = *(const float4*)&g_gate[(size_t)(b * DIN + d) * K_];
        float v = 0.f;
        v = fmaf(gt.x, g_y[((size_t)(b * K_ + 0) * L_ + l) * DIN + d], v);
        v = fmaf(gt.y, g_y[((size_t)(b * K_ + 1) * L_ + l) * DIN + d], v);
        v = fmaf(gt.z, g_y[((size_t)(b * K_ + 2) * L_ + l) * DIN + d], v);
        v = fmaf(gt.w, g_y[((size_t)(b * K_ + 3) * L_ + l) * DIN + d], v);
        a_s[lt][d] = v;
        s1 += v; s2 = fmaf(v, v, s2);
    }
    #pragma unroll
    for (int off = 4; off >= 1; off >>= 1) {
        s1 += __shfl_xor_sync(0xffffffffu, s1, off, 8);
        s2 += __shfl_xor_sync(0xffffffffu, s2, off, 8);
    }
    float mu   = s1 * (1.f / (float)DIN);
    float var  = s2 * (1.f / (float)DIN) - mu * mu;
    float rstd = rsqrtf(var + 1e-5f);
    {
        const float* zrow = g_z + ((size_t)b * L_ + l) * DIN;
        #pragma unroll
        for (int q = 0; q < 24; q++) {
            int d = st + 8 * q;
            float v = a_s[lt][d];
            v = (v - mu) * rstd * lng[d] + lnb[d];
            float z = zrow[d];
            v *= z / (1.f + __expf(-z));
            a_s[lt][d] = v;
        }
    }
    int cg = tid & 31, lg2 = tid >> 5;       // 32 c-groups x 8 l-groups
    float acc[4][3] = {};
    for (int k0 = 0; k0 < DIN; k0 += 32) {
        __syncthreads();
        for (int i = tid; i < 96 * 32; i += 256) {
            int cc = i >> 5, dd = i & 31;
            w_s[cc][dd] = Wout[(size_t)cc * DIN + k0 + dd];
        }
        __syncthreads();
        #pragma unroll 4
        for (int dd = 0; dd < 32; dd++) {
            float av[4];
            #pragma unroll
            for (int ii = 0; ii < 4; ii++) av[ii] = a_s[lg2 * 4 + ii][k0 + dd];
            #pragma unroll
            for (int jj = 0; jj < 3; jj++) {
                float wv = w_s[cg * 3 + jj][dd];
                #pragma unroll
                for (int ii = 0; ii < 4; ii++) acc[ii][jj] = fmaf(av[ii], wv, acc[ii][jj]);
            }
        }
    }
    #pragma unroll
    for (int ii = 0; ii < 4; ii++) {
        int ll = l0 + lg2 * 4 + ii;
        #pragma unroll
        for (int jj = 0; jj < 3; jj++)
            out[((size_t)b * L_ + ll) * C_ + cg * 3 + jj] = acc[ii][jj];
    }
}

// ---------------- launcher ----------------
extern "C" void kernel_launch(void* const* d_in, const int* in_sizes, int n_in,
                              void* d_out, int out_size) {
    const float* x     = (const float*)d_in[0];
    const float* Win   = (const float*)d_in[1];
    const float* convw = (const float*)d_in[2];
    const float* convb = (const float*)d_in[3];
    const float* xpw   = (const float*)d_in[4];
    const float* dtw   = (const float*)d_in[5];
    const float* dtb   = (const float*)d_in[6];
    const float* Alogs = (const float*)d_in[7];
    const float* Dsv   = (const float*)d_in[8];
    const float* gw    = (const float*)d_in[9];
    const float* gb    = (const float*)d_in[10];
    const float* lng   = (const float*)d_in[11];
    const float* lnb   = (const float*)d_in[12];
    const float* Wout  = (const float*)d_in[13];
    const int*   scan  = (const int*)d_in[14];
    float* out = (float*)d_out;

    k_inproj<<<dim3(6, 128), 256>>>(x, Win);
    k_conv  <<<dim3(4, H_, B_), 192>>>(convw, convb);
    k_xproj <<<dim3(L_ / 64, B_ * K_), 128>>>(xpw, scan);
    k_scanA <<<dim3(NC, B_ * K_), 192>>>(dtw, dtb, Alogs, scan);
    k_scanB <<<B_ * K_, 192>>>();
    k_scanC <<<dim3(NC, B_ * K_), 192>>>(dtw, dtb, Alogs, Dsv, scan);
    k_gate  <<<B_, 192>>>(gw, gb);
    k_final <<<dim3(L_ / 32, B_), 256>>>(lng, lnb, Wout, out);
}

// round 3
// speedup vs baseline: 1.2902x; 1.2902x over previous
#include <cuda_runtime.h>
#include <math.h>

// ---------------- problem constants ----------------
#define B_  2
#define H_  64
#define W_  64
#define C_  96
#define DIN 192
#define NST 16
#define RNK 6
#define K_  4
#define L_  4096          // H_*W_
#define NC  64            // scan chunks
#define LC  64            // L_/NC
#define NR  38            // RNK + 2*NST
#define BK_ (B_*K_)

// ---------------- scratch (device globals; no runtime alloc) ----------------
static __device__ float g_xcpre[B_*L_*DIN];          // in-proj x half, (b,l,d)
static __device__ float g_xconv[B_*L_*DIN];          // conv+SiLU out,  (b,l,d)
static __device__ float g_z    [B_*L_*DIN];          // gate z,         (b,l,d)
static __device__ float g_xdbl [BK_*NR*L_];          // x_proj out, ((b*K+k)*38+r)*L + l
static __device__ float g_chP  [BK_*NC*NST*DIN];     // per-chunk prod(dA), [(bk,c,n),d]
static __device__ float g_chQ  [BK_*NC*NST*DIN];     // per-chunk affine offset
static __device__ float g_h0   [BK_*NC*NST*DIN];     // chunk initial states
static __device__ float g_yloc [BK_*L_*DIN];         // local scan y (scan order), (bk,l,d)
static __device__ float g_sd   [BK_*L_*DIN];         // inclusive cumsum(delta) within chunk
static __device__ float g_y    [BK_*L_*DIN];         // scattered y, ((bk)*L + pos)*DIN + d
static __device__ float g_psum [BK_*NC*DIN];         // per-chunk pooled partial sums
static __device__ float g_gate [B_*DIN*K_];          // sigmoid gates

// ---------------- helpers ----------------
__device__ __forceinline__ float softplusf(float t) {
    return (t > 15.f) ? t : log1pf(expf(t));
}
// p[n] = e^(n+1), log-depth
__device__ __forceinline__ void pow_ladder(float e, float* p) {
    float e2 = e * e, e4 = e2 * e2, e8 = e4 * e4;
    p[0] = e;       p[1] = e2;      p[2] = e2 * e;  p[3] = e4;
    p[4] = e4 * e;  p[5] = e4 * e2; p[6] = e4 * p[2]; p[7] = e8;
    p[8] = e8 * e;  p[9] = e8 * e2; p[10] = e8 * p[2]; p[11] = e8 * e4;
    p[12] = e8 * p[4]; p[13] = e8 * p[5]; p[14] = e8 * p[6]; p[15] = e8 * e8;
}

// ---------------- kernel 1: in_proj GEMM  (8192x384x96) ----------------
__global__ __launch_bounds__(256) void k_inproj(const float* __restrict__ x,
                                                const float* __restrict__ Win) {
    __shared__ float As[32][68];
    __shared__ float Bs[32][68];
    int tid = threadIdx.x;
    int m0 = blockIdx.y * 64;
    int n0 = blockIdx.x * 64;
    int tm = tid & 15, tn = tid >> 4;
    float acc[4][4] = {};
    for (int k0 = 0; k0 < 96; k0 += 32) {
        #pragma unroll
        for (int q = 0; q < 2; q++) {
            int f = tid * 2 + q;
            int m = f >> 3, kq = f & 7;
            float4 v = *(const float4*)&x[(size_t)(m0 + m) * 96 + k0 + kq * 4];
            As[kq*4+0][m] = v.x; As[kq*4+1][m] = v.y;
            As[kq*4+2][m] = v.z; As[kq*4+3][m] = v.w;
        }
        #pragma unroll
        for (int q = 0; q < 2; q++) {
            int f = tid * 2 + q;
            int n = f >> 3, kq = f & 7;
            float4 v = *(const float4*)&Win[(size_t)(n0 + n) * 96 + k0 + kq * 4];
            Bs[kq*4+0][n] = v.x; Bs[kq*4+1][n] = v.y;
            Bs[kq*4+2][n] = v.z; Bs[kq*4+3][n] = v.w;
        }
        __syncthreads();
        #pragma unroll
        for (int kk = 0; kk < 32; kk++) {
            float4 a4 = *(const float4*)&As[kk][tm*4];
            float4 b4 = *(const float4*)&Bs[kk][tn*4];
            float av[4] = {a4.x, a4.y, a4.z, a4.w};
            float bv[4] = {b4.x, b4.y, b4.z, b4.w};
            #pragma unroll
            for (int i = 0; i < 4; i++)
                #pragma unroll
                for (int j = 0; j < 4; j++)
                    acc[i][j] = fmaf(av[i], bv[j], acc[i][j]);
        }
        __syncthreads();
    }
    #pragma unroll
    for (int i = 0; i < 4; i++) {
        int m = m0 + tm * 4 + i;
        #pragma unroll
        for (int j = 0; j < 4; j++) {
            int n = n0 + tn * 4 + j;
            if (n < DIN) g_xcpre[(size_t)m * DIN + n]        = acc[i][j];
            else         g_z    [(size_t)m * DIN + (n - DIN)] = acc[i][j];
        }
    }
}

// ---------------- kernel 2: depthwise 3x3 conv + bias + SiLU ----------------
__global__ __launch_bounds__(192) void k_conv(const float* __restrict__ cw,
                                              const float* __restrict__ cb) {
    int d = threadIdx.x;
    int b = blockIdx.z, y = blockIdx.y, xt = blockIdx.x;
    float w9[9];
    #pragma unroll
    for (int i = 0; i < 9; i++) w9[i] = cw[d * 9 + i];
    float bias = cb[d];
    const float* src = g_xcpre + (size_t)b * L_ * DIN;
    float*       dst = g_xconv + (size_t)b * L_ * DIN;
    for (int xi = 0; xi < 16; xi++) {
        int xx0 = xt * 16 + xi;
        float acc = bias;
        #pragma unroll
        for (int dy = -1; dy <= 1; dy++) {
            int yy = y + dy;
            if ((unsigned)yy >= 64u) continue;
            #pragma unroll
            for (int dx = -1; dx <= 1; dx++) {
                int xx = xx0 + dx;
                if ((unsigned)xx >= 64u) continue;
                acc = fmaf(src[(size_t)(yy * 64 + xx) * DIN + d], w9[(dy+1)*3 + dx+1], acc);
            }
        }
        float s = 1.f / (1.f + __expf(-acc));
        dst[(size_t)(y * 64 + xx0) * DIN + d] = acc * s;
    }
}

// ---------------- kernel 3: x_proj GEMM with gather ----------------
__global__ __launch_bounds__(128) void k_xproj(const float* __restrict__ xpw,
                                               const int*   __restrict__ scan) {
    __shared__ float xs_s[32][68];
    __shared__ float ws  [40][33];
    __shared__ int   sid [64];
    int tid = threadIdx.x;
    int l0  = blockIdx.x * 64;
    int bk  = blockIdx.y;
    int b = bk >> 2, k = bk & 3;
    if (tid < 64) sid[tid] = scan[(size_t)k * L_ + l0 + tid];
    int lg = tid >> 3, rg = tid & 7;
    float acc[5][4] = {};
    const float* xc = g_xconv + (size_t)b * L_ * DIN;
    for (int k0 = 0; k0 < DIN; k0 += 32) {
        __syncthreads();
        for (int i = tid; i < NR * 32; i += 128) {
            int r = i >> 5, c = i & 31;
            ws[r][c] = xpw[(size_t)(k * NR + r) * DIN + k0 + c];
        }
        if (tid < 64) ws[38 + (tid >> 5)][tid & 31] = 0.f;
        {
            int l = tid >> 1, half = (tid & 1) * 16;
            const float* p = &xc[(size_t)sid[l] * DIN + k0 + half];
            #pragma unroll
            for (int q = 0; q < 16; q += 4) {
                float4 v = *(const float4*)(p + q);
                xs_s[half+q+0][l] = v.x; xs_s[half+q+1][l] = v.y;
                xs_s[half+q+2][l] = v.z; xs_s[half+q+3][l] = v.w;
            }
        }
        __syncthreads();
        #pragma unroll
        for (int kk = 0; kk < 32; kk++) {
            float4 a4 = *(const float4*)&xs_s[kk][lg * 4];
            float av[4] = {a4.x, a4.y, a4.z, a4.w};
            #pragma unroll
            for (int j = 0; j < 5; j++) {
                float wv = ws[rg + 8 * j][kk];
                #pragma unroll
                for (int i = 0; i < 4; i++) acc[j][i] = fmaf(wv, av[i], acc[j][i]);
            }
        }
    }
    float* outp = g_xdbl + (size_t)bk * NR * L_;
    #pragma unroll
    for (int j = 0; j < 5; j++) {
        int r = rg + 8 * j;
        if (r < NR) {
            #pragma unroll
            for (int i = 0; i < 4; i++)
                outp[(size_t)r * L_ + l0 + lg * 4 + i] = acc[j][i];
        }
    }
}

// ---------------- kernel 4: scan phase A (local scan + sd + chunk transitions)
__global__ __launch_bounds__(192) void k_scanA(const float* __restrict__ dtw,
                                               const float* __restrict__ dtb,
                                               const float* __restrict__ Alogs,
                                               const float* __restrict__ Dsv,
                                               const int*   __restrict__ scan) {
    __shared__ float sx[NR][LC];
    __shared__ int   ssid[LC];
    int d  = threadIdx.x;
    int c  = blockIdx.x;
    int bk = blockIdx.y;
    int b = bk >> 2, k = bk & 3;
    int l0 = c * LC;
    const float* xd = g_xdbl + (size_t)bk * NR * L_;
    for (int i = d; i < NR * LC; i += 192) {
        int r = i >> 6, q = i & 63;
        sx[r][q] = xd[(size_t)r * L_ + l0 + q];
    }
    if (d < LC) ssid[d] = scan[(size_t)k * L_ + l0 + d];
    int kd = k * DIN + d;
    float wr[RNK];
    #pragma unroll
    for (int r = 0; r < RNK; r++) wr[r] = dtw[(size_t)kd * RNK + r];
    float tb = dtb[kd];
    float Dv = Dsv[kd];
    float a[NST]; bool fast = true;
    #pragma unroll
    for (int n = 0; n < NST; n++) {
        a[n] = -expf(Alogs[(size_t)kd * NST + n]);
        fast = fast && (fabsf(a[n] + (float)(n + 1)) <= 1e-3f * (float)(n + 1));
    }
    __syncthreads();
    const float* xc = g_xconv + (size_t)b * L_ * DIN;
    float h[NST];
    #pragma unroll
    for (int n = 0; n < NST; n++) h[n] = 0.f;
    float sdv = 0.f;
    if (fast) {
        #pragma unroll 2
        for (int i = 0; i < LC; i++) {
            float xv = xc[(size_t)ssid[i] * DIN + d];
            float t = tb;
            #pragma unroll
            for (int r = 0; r < RNK; r++) t = fmaf(wr[r], sx[r][i], t);
            float delta = softplusf(t);
            sdv += delta;
            float du = delta * xv;
            float p[NST];
            pow_ladder(expf(-delta), p);
            float ys = 0.f;
            #pragma unroll
            for (int n = 0; n < NST; n++)
                h[n] = fmaf(p[n], h[n], du * sx[RNK + n][i]);
            #pragma unroll
            for (int n = 0; n < NST; n++)
                ys = fmaf(h[n], sx[RNK + NST + n][i], ys);
            ys = fmaf(Dv, xv, ys);
            size_t gi = ((size_t)bk * L_ + l0 + i) * DIN + d;
            g_yloc[gi] = ys;
            g_sd[gi]   = sdv;
        }
    } else {
        #pragma unroll 1
        for (int i = 0; i < LC; i++) {
            float xv = xc[(size_t)ssid[i] * DIN + d];
            float t = tb;
            #pragma unroll
            for (int r = 0; r < RNK; r++) t = fmaf(wr[r], sx[r][i], t);
            float delta = softplusf(t);
            sdv += delta;
            float du = delta * xv;
            float ys = 0.f;
            #pragma unroll
            for (int n = 0; n < NST; n++) {
                float dA = __expf(delta * a[n]);
                h[n] = fmaf(dA, h[n], du * sx[RNK + n][i]);
                ys = fmaf(h[n], sx[RNK + NST + n][i], ys);
            }
            ys = fmaf(Dv, xv, ys);
            size_t gi = ((size_t)bk * L_ + l0 + i) * DIN + d;
            g_yloc[gi] = ys;
            g_sd[gi]   = sdv;
        }
    }
    // chunk transition: P[n] = exp(a[n] * sd_total), Q[n] = h[n]
    size_t base = ((size_t)(bk * NC + c) * NST) * DIN + d;
    if (fast) {
        float p[NST];
        pow_ladder(expf(-sdv), p);
        #pragma unroll
        for (int n = 0; n < NST; n++) {
            g_chP[base + (size_t)n * DIN] = p[n];
            g_chQ[base + (size_t)n * DIN] = h[n];
        }
    } else {
        #pragma unroll
        for (int n = 0; n < NST; n++) {
            g_chP[base + (size_t)n * DIN] = __expf(a[n] * sdv);
            g_chQ[base + (size_t)n * DIN] = h[n];
        }
    }
}

// ---------------- kernel 5: scan phase B (serial chunk chain) ----------------
__global__ __launch_bounds__(192) void k_scanB() {
    int n  = blockIdx.x;     // state index
    int bk = blockIdx.y;
    int d  = threadIdx.x;
    float h = 0.f;
    for (int c = 0; c < NC; c++) {
        size_t base = ((size_t)(bk * NC + c) * NST + n) * DIN + d;
        g_h0[base] = h;
        h = fmaf(g_chP[base], h, g_chQ[base]);
    }
}

// ---------------- kernel 6: scan phase C (parallel correction + scatter + pool)
__global__ __launch_bounds__(192) void k_scanC(const float* __restrict__ Alogs,
                                               const int*   __restrict__ scan) {
    __shared__ float sC[NST][LC];
    __shared__ int   ssid[LC];
    int d  = threadIdx.x;
    int c  = blockIdx.x;
    int bk = blockIdx.y;
    int k = bk & 3;
    int l0 = c * LC;
    const float* xd = g_xdbl + (size_t)bk * NR * L_;
    for (int i = d; i < NST * LC; i += 192) {
        int n = i >> 6, q = i & 63;
        sC[n][q] = xd[(size_t)(RNK + NST + n) * L_ + l0 + q];
    }
    if (d < LC) ssid[d] = scan[(size_t)k * L_ + l0 + d];
    int kd = k * DIN + d;
    float a[NST]; bool fast = true;
    float h0[NST]; bool any = false;
    size_t base = ((size_t)(bk * NC + c) * NST) * DIN + d;
    #pragma unroll
    for (int n = 0; n < NST; n++) {
        a[n] = -expf(Alogs[(size_t)kd * NST + n]);
        fast = fast && (fabsf(a[n] + (float)(n + 1)) <= 1e-3f * (float)(n + 1));
        h0[n] = g_h0[base + (size_t)n * DIN];
        any = any || (h0[n] != 0.f);
    }
    __syncthreads();
    float* yp = g_y + (size_t)bk * L_ * DIN;
    float sacc = 0.f;
    if (!any) {
        #pragma unroll 4
        for (int i = 0; i < LC; i++) {
            size_t gi = ((size_t)bk * L_ + l0 + i) * DIN + d;
            float yv = g_yloc[gi];
            yp[(size_t)ssid[i] * DIN + d] = yv;
            sacc += yv;
        }
    } else if (fast) {
        #pragma unroll 2
        for (int i = 0; i < LC; i++) {
            size_t gi = ((size_t)bk * L_ + l0 + i) * DIN + d;
            float yv = g_yloc[gi];
            float p[NST];
            pow_ladder(expf(-g_sd[gi]), p);
            float corr = 0.f;
            #pragma unroll
            for (int n = 0; n < NST; n++)
                corr = fmaf(sC[n][i] * h0[n], p[n], corr);
            yv += corr;
            yp[(size_t)ssid[i] * DIN + d] = yv;
            sacc += yv;
        }
    } else {
        #pragma unroll 1
        for (int i = 0; i < LC; i++) {
            size_t gi = ((size_t)bk * L_ + l0 + i) * DIN + d;
            float yv = g_yloc[gi];
            float sdv = g_sd[gi];
            float corr = 0.f;
            #pragma unroll
            for (int n = 0; n < NST; n++)
                corr = fmaf(sC[n][i] * h0[n], __expf(a[n] * sdv), corr);
            yv += corr;
            yp[(size_t)ssid[i] * DIN + d] = yv;
            sacc += yv;
        }
    }
    g_psum[((size_t)bk * NC + c) * DIN + d] = sacc;
}

// ---------------- kernel 7: gates ----------------
__global__ __launch_bounds__(192) void k_gate(const float* __restrict__ gw,
                                              const float* __restrict__ gb) {
    int b = blockIdx.x, d = threadIdx.x;
    float pooled[K_];
    #pragma unroll
    for (int k = 0; k < K_; k++) {
        float s = 0.f;
        for (int c = 0; c < NC; c++)
            s += g_psum[((size_t)(b * K_ + k) * NC + c) * DIN + d];
        pooled[k] = s * (1.f / (float)L_);
    }
    #pragma unroll
    for (int o = 0; o < K_; o++) {
        float acc = gb[d * K_ + o];
        #pragma unroll
        for (int i = 0; i < K_; i++)
            acc = fmaf(pooled[i], gw[(size_t)(d * K_ + o) * K_ + i], acc);
        g_gate[(size_t)(b * DIN + d) * K_ + o] = 1.f / (1.f + __expf(-acc));
    }
}

// ---------------- kernel 8: gate-combine + LayerNorm + SiLU(z) + out GEMM ----
__global__ __launch_bounds__(256) void k_final(const float* __restrict__ lng,
                                               const float* __restrict__ lnb,
                                               const float* __restrict__ Wout,
                                               float* __restrict__ out) {
    __shared__ float a_s[32][193];
    __shared__ float w_s[96][33];
    int tid = threadIdx.x;
    int b  = blockIdx.y;
    int l0 = blockIdx.x * 32;
    int lt = tid >> 3, st = tid & 7;
    int l = l0 + lt;
    float s1 = 0.f, s2 = 0.f;
    #pragma unroll
    for (int q = 0; q < 24; q++) {
        int d = st + 8 * q;
        float4 gt = *(const float4*)&g_gate[(size_t)(b * DIN + d) * K_];
        float v = 0.f;
        v = fmaf(gt.x, g_y[((size_t)(b * K_ + 0) * L_ + l) * DIN + d], v);
        v = fmaf(gt.y, g_y[((size_t)(b * K_ + 1) * L_ + l) * DIN + d], v);
        v = fmaf(gt.z, g_y[((size_t)(b * K_ + 2) * L_ + l) * DIN + d], v);
        v = fmaf(gt.w, g_y[((size_t)(b * K_ + 3) * L_ + l) * DIN + d], v);
        a_s[lt][d] = v;
        s1 += v; s2 = fmaf(v, v, s2);
    }
    #pragma unroll
    for (int off = 4; off >= 1; off >>= 1) {
        s1 += __shfl_xor_sync(0xffffffffu, s1, off, 8);
        s2 += __shfl_xor_sync(0xffffffffu, s2, off, 8);
    }
    float mu   = s1 * (1.f / (float)DIN);
    float var  = s2 * (1.f / (float)DIN) - mu * mu;
    float rstd = rsqrtf(var + 1e-5f);
    {
        const float* zrow = g_z + ((size_t)b * L_ + l) * DIN;
        #pragma unroll
        for (int q = 0; q < 24; q++) {
            int d = st + 8 * q;
            float v = a_s[lt][d];
            v = (v - mu) * rstd * lng[d] + lnb[d];
            float z = zrow[d];
            v *= z / (1.f + __expf(-z));
            a_s[lt][d] = v;
        }
    }
    int cg = tid & 31, lg2 = tid >> 5;
    float acc[4][3] = {};
    for (int k0 = 0; k0 < DIN; k0 += 32) {
        __syncthreads();
        for (int i = tid; i < 96 * 32; i += 256) {
            int cc = i >> 5, dd = i & 31;
            w_s[cc][dd] = Wout[(size_t)cc * DIN + k0 + dd];
        }
        __syncthreads();
        #pragma unroll 4
        for (int dd = 0; dd < 32; dd++) {
            float av[4];
            #pragma unroll
            for (int ii = 0; ii < 4; ii++) av[ii] = a_s[lg2 * 4 + ii][k0 + dd];
            #pragma unroll
            for (int jj = 0; jj < 3; jj++) {
                float wv = w_s[cg * 3 + jj][dd];
                #pragma unroll
                for (int ii = 0; ii < 4; ii++) acc[ii][jj] = fmaf(av[ii], wv, acc[ii][jj]);
            }
        }
    }
    #pragma unroll
    for (int ii = 0; ii < 4; ii++) {
        int ll = l0 + lg2 * 4 + ii;
        #pragma unroll
        for (int jj = 0; jj < 3; jj++)
            out[((size_t)b * L_ + ll) * C_ + cg * 3 + jj] = acc[ii][jj];
    }
}

// ---------------- launcher ----------------
extern "C" void kernel_launch(void* const* d_in, const int* in_sizes, int n_in,
                              void* d_out, int out_size) {
    const float* x     = (const float*)d_in[0];
    const float* Win   = (const float*)d_in[1];
    const float* convw = (const float*)d_in[2];
    const float* convb = (const float*)d_in[3];
    const float* xpw   = (const float*)d_in[4];
    const float* dtw   = (const float*)d_in[5];
    const float* dtb   = (const float*)d_in[6];
    const float* Alogs = (const float*)d_in[7];
    const float* Dsv   = (const float*)d_in[8];
    const float* gw    = (const float*)d_in[9];
    const float* gb    = (const float*)d_in[10];
    const float* lng   = (const float*)d_in[11];
    const float* lnb   = (const float*)d_in[12];
    const float* Wout  = (const float*)d_in[13];
    const int*   scan  = (const int*)d_in[14];
    float* out = (float*)d_out;

    k_inproj<<<dim3(6, 128), 256>>>(x, Win);
    k_conv  <<<dim3(4, H_, B_), 192>>>(convw, convb);
    k_xproj <<<dim3(L_ / 64, BK_), 128>>>(xpw, scan);
    k_scanA <<<dim3(NC, BK_), 192>>>(dtw, dtb, Alogs, Dsv, scan);
    k_scanB <<<dim3(NST, BK_), 192>>>();
    k_scanC <<<dim3(NC, BK_), 192>>>(Alogs, scan);
    k_gate  <<<B_, 192>>>(gw, gb);
    k_final <<<dim3(L_ / 32, B_), 256>>>(lng, lnb, Wout, out);
}